// round 13
// baseline (speedup 1.0000x reference)
#include <cuda_runtime.h>
#include <cuda_bf16.h>
#include <math.h>
#include <stdint.h>

#define BATCH 256
#define QTR   64
#define NSTREAMS 4
#define CCH   256
#define MMSP  196
#define KPAD  224
#define DTRI  32896
#define MAT   65536

// bf16 hi/lo planes
__device__ __nv_bfloat16 g_Xhi[(size_t)BATCH * CCH * KPAD];
__device__ __nv_bfloat16 g_Xlo[(size_t)BATCH * CCH * KPAD];
__device__ __nv_bfloat16 g_Phi[(size_t)BATCH * MAT];
__device__ __nv_bfloat16 g_Plo[(size_t)BATCH * MAT];
__device__ __nv_bfloat16 g_Qhi[(size_t)BATCH * MAT];
__device__ __nv_bfloat16 g_Qlo[(size_t)BATCH * MAT];
__device__ __nv_bfloat16 g_Rhi[(size_t)BATCH * MAT];
__device__ __nv_bfloat16 g_Rlo[(size_t)BATCH * MAT];
__device__ __nv_bfloat16 g_Shi[(size_t)BATCH * MAT];
__device__ __nv_bfloat16 g_Slo[(size_t)BATCH * MAT];
__device__ __nv_bfloat16 g_Thi[(size_t)BATCH * MAT];
__device__ __nv_bfloat16 g_Tlo[(size_t)BATCH * MAT];
__device__ float g_part[BATCH * 3 * 2];
__device__ float g_sums[BATCH * CCH];
__device__ float g_norm[BATCH];

// ---------------------------------------------------------------------------
__device__ __forceinline__ uint32_t smem_u32(const void* p) {
    uint32_t a;
    asm("{ .reg .u64 t; cvta.to.shared.u64 t, %1; cvt.u32.u64 %0, t; }" : "=r"(a) : "l"(p));
    return a;
}
__device__ __forceinline__ void ldsm4(uint32_t addr, uint32_t* r) {
    asm volatile("ldmatrix.sync.aligned.m8n8.x4.shared.b16 {%0,%1,%2,%3}, [%4];"
        : "=r"(r[0]), "=r"(r[1]), "=r"(r[2]), "=r"(r[3]) : "r"(addr));
}
__device__ __forceinline__ void mma_bf16(float* d, const uint32_t* a,
                                         uint32_t b0, uint32_t b1) {
    asm volatile("mma.sync.aligned.m16n8k16.row.col.f32.bf16.bf16.f32 "
                 "{%0,%1,%2,%3}, {%4,%5,%6,%7}, {%8,%9}, {%0,%1,%2,%3};"
        : "+f"(d[0]), "+f"(d[1]), "+f"(d[2]), "+f"(d[3])
        : "r"(a[0]), "r"(a[1]), "r"(a[2]), "r"(a[3]), "r"(b0), "r"(b1));
}
__device__ __forceinline__ void cp16(uint32_t dst, const void* src) {
    asm volatile("cp.async.cg.shared.global [%0], [%1], 16;" :: "r"(dst), "l"(src));
}
#define CP_COMMIT()  asm volatile("cp.async.commit_group;" ::: "memory")
#define CP_WAIT(N)   asm volatile("cp.async.wait_group %0;" :: "n"(N) : "memory")

#define ABUF(b)   ((b) * 32768)
#define BBUF(b)   ((b) * 32768 + 16384)
#define SMEM_TOTAL (3 * 32768)
#define STG_LDS   132

__device__ __forceinline__ void split_pack(float a, float b, uint32_t& hi, uint32_t& lo) {
    __nv_bfloat16 ha = __float2bfloat16(a);
    __nv_bfloat16 hb = __float2bfloat16(b);
    __nv_bfloat162 hh; hh.x = ha; hh.y = hb;
    __nv_bfloat162 ll;
    ll.x = __float2bfloat16(a - __bfloat162float(ha));
    ll.y = __float2bfloat16(b - __bfloat162float(hb));
    hi = *reinterpret_cast<uint32_t*>(&hh);
    lo = *reinterpret_cast<uint32_t*>(&ll);
}

// ---------------------------------------------------------------------------
// Symmetric-output batched GEMM on bf16 hi/lo planes, 3-product split.
// bx=0 -> (0,0); 1 -> (0,128) (+ smem-transposed mirror); 2 -> (128,128).
// bx in [3,6): second GEMM of a fused pair (mode forced 0).
// modes: 0 planes; 1 TI planes; 2 fused triu-FC partials; 3 cov (Ahat + ZY)
// b = blockIdx.y + bbase (multi-stream batch slices)
// ---------------------------------------------------------------------------
__global__ __launch_bounds__(256, 2)
void gemm_tc(const __nv_bfloat16* __restrict__ Ahi, const __nv_bfloat16* __restrict__ Alo,
             const __nv_bfloat16* __restrict__ Bhi, const __nv_bfloat16* __restrict__ Blo,
             __nv_bfloat16* __restrict__ Chi, __nv_bfloat16* __restrict__ Clo,
             __nv_bfloat16* __restrict__ C2hi, __nv_bfloat16* __restrict__ C2lo,
             const __nv_bfloat16* A2hi, const __nv_bfloat16* A2lo,
             const __nv_bfloat16* B2hi, const __nv_bfloat16* B2lo,
             __nv_bfloat16* D2hi, __nv_bfloat16* D2lo,
             const float* __restrict__ fcw, float* __restrict__ part,
             int ldk, long strAB, int K, int mode, int bbase,
             const float* __restrict__ norm, const float* __restrict__ sums) {
    extern __shared__ char smem[];
    const uint32_t smb = smem_u32(smem);

    const int tid  = threadIdx.x;
    const int wid  = tid >> 5;
    const int lane = tid & 31;
    const int wm = wid >> 2;
    const int wn = wid & 3;
    const int g  = lane >> 2;
    const int t  = lane & 3;

    int bx = blockIdx.x;
    const int b = blockIdx.y + bbase;
    const int kflip = (blockIdx.x ^ blockIdx.y) & 1;   // de-phase co-resident CTAs

    const __nv_bfloat16 *pAh = Ahi, *pAl = Alo, *pBh = Bhi, *pBl = Blo;
    __nv_bfloat16 *pCh = Chi, *pCl = Clo;
    if (bx >= 3) {
        bx -= 3;
        pAh = A2hi; pAl = A2lo; pBh = B2hi; pBl = B2lo;
        pCh = D2hi; pCl = D2lo;
        mode = 0;
    }
    const int m0 = (bx == 2) ? 128 : 0;
    const int n0 = (bx >= 1) ? 128 : 0;
    const bool offdiag = (m0 != n0);

    const __nv_bfloat16* Abh = pAh + (size_t)b * strAB + (size_t)m0 * ldk;
    const __nv_bfloat16* Abl = pAl + (size_t)b * strAB + (size_t)m0 * ldk;
    const __nv_bfloat16* Bbh = pBh + (size_t)b * strAB + (size_t)n0 * ldk;
    const __nv_bfloat16* Bbl = pBl + (size_t)b * strAB + (size_t)n0 * ldk;

    const int r0c = (tid + 0)   >> 2, c0c = tid & 3;
    const int r1c = (tid + 256) >> 2;
    const int nch = K >> 5;

    float acc[4][4][4];
#pragma unroll
    for (int i = 0; i < 4; ++i)
#pragma unroll
        for (int j = 0; j < 4; ++j)
#pragma unroll
            for (int k = 0; k < 4; ++k) acc[i][j][k] = 0.f;

    auto issue = [&](int ch, int buf) {
        int col = (ch << 5) + c0c * 8;
        uint32_t swh0 = (uint32_t)((c0c       ^ (r0c & 7)) << 4);
        uint32_t swl0 = (uint32_t)(((4 + c0c) ^ (r0c & 7)) << 4);
        uint32_t swh1 = (uint32_t)((c0c       ^ (r1c & 7)) << 4);
        uint32_t swl1 = (uint32_t)(((4 + c0c) ^ (r1c & 7)) << 4);
        uint32_t dA0 = smb + ABUF(buf) + r0c * 128;
        uint32_t dB0 = smb + BBUF(buf) + r0c * 128;
        uint32_t dA1 = smb + ABUF(buf) + r1c * 128;
        uint32_t dB1 = smb + BBUF(buf) + r1c * 128;
        cp16(dA0 + swh0, Abh + (size_t)r0c * ldk + col);
        cp16(dA0 + swl0, Abl + (size_t)r0c * ldk + col);
        cp16(dB0 + swh0, Bbh + (size_t)r0c * ldk + col);
        cp16(dB0 + swl0, Bbl + (size_t)r0c * ldk + col);
        cp16(dA1 + swh1, Abh + (size_t)r1c * ldk + col);
        cp16(dA1 + swl1, Abl + (size_t)r1c * ldk + col);
        cp16(dB1 + swh1, Bbh + (size_t)r1c * ldk + col);
        cp16(dB1 + swl1, Bbl + (size_t)r1c * ldk + col);
    };

    issue(0, 0); CP_COMMIT();
    if (nch > 1) { issue(1, 1); CP_COMMIT(); }

    for (int ch = 0; ch < nch; ++ch) {
        if (ch + 1 < nch) { CP_WAIT(1); } else { CP_WAIT(0); }
        __syncthreads();

        const int buf = ch % 3;
        const uint32_t smA = smb + ABUF(buf);
        const uint32_t smB = smb + BBUF(buf);

#pragma unroll
        for (int kss = 0; kss < 2; ++kss) {
            const int ks = kss ^ kflip;
            // -- hi-plane frags
            uint32_t ah[4][4], bh[2][4];
#pragma unroll
            for (int mt = 0; mt < 4; ++mt) {
                int r = wm * 64 + mt * 16 + (lane & 15);
                int cb = ks * 2 + (lane >> 4);
                ldsm4(smA + r * 128 + ((cb ^ (r & 7)) << 4), ah[mt]);
            }
#pragma unroll
            for (int bt = 0; bt < 2; ++bt) {
                int r = wn * 32 + bt * 16 + ((lane >> 4) << 3) + (lane & 7);
                int cb = ks * 2 + ((lane >> 3) & 1);
                ldsm4(smB + r * 128 + ((cb ^ (r & 7)) << 4), bh[bt]);
            }
            // -- hh products (tensor shadow for what follows)
#pragma unroll
            for (int mt = 0; mt < 4; ++mt)
#pragma unroll
                for (int nt = 0; nt < 4; ++nt) {
                    const uint32_t* bhp = &bh[nt >> 1][(nt & 1) * 2];
                    mma_bf16(acc[mt][nt], ah[mt], bhp[0], bhp[1]);
                }
            // -- lo-plane frags + next-chunk cp.async, under hh MMA shadow
            uint32_t al[4][4], bl[2][4];
#pragma unroll
            for (int mt = 0; mt < 4; ++mt) {
                int r = wm * 64 + mt * 16 + (lane & 15);
                int cb = ks * 2 + (lane >> 4);
                ldsm4(smA + r * 128 + (((4 + cb) ^ (r & 7)) << 4), al[mt]);
            }
#pragma unroll
            for (int bt = 0; bt < 2; ++bt) {
                int r = wn * 32 + bt * 16 + ((lane >> 4) << 3) + (lane & 7);
                int cb = ks * 2 + ((lane >> 3) & 1);
                ldsm4(smB + r * 128 + (((4 + cb) ^ (r & 7)) << 4), bl[bt]);
            }
            if (kss == 0 && ch + 2 < nch) { issue(ch + 2, (ch + 2) % 3); CP_COMMIT(); }
            // -- cross products
#pragma unroll
            for (int mt = 0; mt < 4; ++mt)
#pragma unroll
                for (int nt = 0; nt < 4; ++nt) {
                    const uint32_t* blp = &bl[nt >> 1][(nt & 1) * 2];
                    mma_bf16(acc[mt][nt], ah[mt], blp[0], blp[1]);
                }
#pragma unroll
            for (int mt = 0; mt < 4; ++mt)
#pragma unroll
                for (int nt = 0; nt < 4; ++nt) {
                    const uint32_t* bhp = &bh[nt >> 1][(nt & 1) * 2];
                    mma_bf16(acc[mt][nt], al[mt], bhp[0], bhp[1]);
                }
        }
    }

    const size_t cbase = (size_t)b * MAT;

    if (mode == 2) {
        float sc = sqrtf(norm[b]);
        float f0 = 0.f, f1 = 0.f;
#pragma unroll
        for (int mt = 0; mt < 4; ++mt) {
            int r0 = m0 + wm * 64 + mt * 16 + g;
#pragma unroll
            for (int nt = 0; nt < 4; ++nt) {
                int c0 = n0 + wn * 32 + nt * 8 + 2 * t;
                float* d = acc[mt][nt];
#pragma unroll
                for (int half = 0; half < 2; ++half) {
                    int gi = r0 + half * 8;
                    float v0 = d[half * 2 + 0] * sc;
                    float v1 = d[half * 2 + 1] * sc;
                    int tt = gi * CCH - ((gi * (gi + 1)) >> 1) + c0;
                    if (offdiag || c0 >= gi) {
                        f0 += v0 * __ldg(fcw + tt);
                        f1 += v0 * __ldg(fcw + DTRI + tt);
                    }
                    if (offdiag || c0 + 1 >= gi) {
                        f0 += v1 * __ldg(fcw + tt + 1);
                        f1 += v1 * __ldg(fcw + DTRI + tt + 1);
                    }
                }
            }
        }
        __syncthreads();
        float* red = reinterpret_cast<float*>(smem);
        red[tid] = f0; red[256 + tid] = f1;
        __syncthreads();
        for (int off = 128; off > 0; off >>= 1) {
            if (tid < off) { red[tid] += red[tid + off]; red[256 + tid] += red[256 + tid + off]; }
            __syncthreads();
        }
        if (tid == 0) {
            part[(b * 3 + bx) * 2 + 0] = red[0];
            part[(b * 3 + bx) * 2 + 1] = red[256];
        }
        return;
    }

    float invMn = 0.0f;
    const float* sb = 0;
    if (mode == 3) {
        invMn = 1.0f / (196.0f * norm[b]);
        sb = sums + b * CCH;
    }

    __syncthreads();
    float* stg = reinterpret_cast<float*>(smem);

#pragma unroll
    for (int mt = 0; mt < 4; ++mt) {
        int r0 = m0 + wm * 64 + mt * 16 + g;
#pragma unroll
        for (int nt = 0; nt < 4; ++nt) {
            int c0 = n0 + wn * 32 + nt * 8 + 2 * t;
            float* d = acc[mt][nt];
#pragma unroll
            for (int half = 0; half < 2; ++half) {
                int gi = r0 + half * 8;
                float v0 = d[half * 2 + 0];
                float v1 = d[half * 2 + 1];
                size_t off = cbase + (size_t)gi * CCH + c0;
                if (mode == 1) {
                    v0 = (gi == c0     ? 1.5f : 0.0f) - 0.5f * v0;
                    v1 = (gi == c0 + 1 ? 1.5f : 0.0f) - 0.5f * v1;
                } else if (mode == 3) {
                    float si = sb[gi] * (1.0f / 196.0f);
                    v0 = (v0 - si * sb[c0])     * invMn;
                    v1 = (v1 - si * sb[c0 + 1]) * invMn;
                    float w0 = (gi == c0     ? 1.5f : 0.0f) - 0.5f * v0;
                    float w1 = (gi == c0 + 1 ? 1.5f : 0.0f) - 0.5f * v1;
                    uint32_t whi, wlo;
                    split_pack(w0, w1, whi, wlo);
                    *reinterpret_cast<uint32_t*>(C2hi + off) = whi;
                    *reinterpret_cast<uint32_t*>(C2lo + off) = wlo;
                }
                uint32_t hi, lo;
                split_pack(v0, v1, hi, lo);
                *reinterpret_cast<uint32_t*>(pCh + off) = hi;
                *reinterpret_cast<uint32_t*>(pCl + off) = lo;
                if (offdiag) {
                    int lr = gi - m0, lc = c0 - n0;
                    stg[lr * STG_LDS + lc]     = v0;
                    stg[lr * STG_LDS + lc + 1] = v1;
                }
            }
        }
    }

    if (offdiag) {
        __syncthreads();
        const int j  = tid & 127;
        const int ib = tid >> 7;
#pragma unroll
        for (int s = 0; s < 8; ++s) {
            int i0 = ib * 64 + s * 8;
            uint32_t hp[4], lp[4], wh[4], wl[4];
#pragma unroll
            for (int k = 0; k < 4; ++k) {
                float a = stg[(i0 + 2 * k)     * STG_LDS + j];
                float c = stg[(i0 + 2 * k + 1) * STG_LDS + j];
                split_pack(a, c, hp[k], lp[k]);
                if (mode == 3) split_pack(-0.5f * a, -0.5f * c, wh[k], wl[k]);
            }
            size_t moff = cbase + (size_t)(n0 + j) * CCH + (m0 + i0);
            *reinterpret_cast<uint4*>(pCh + moff) = make_uint4(hp[0], hp[1], hp[2], hp[3]);
            *reinterpret_cast<uint4*>(pCl + moff) = make_uint4(lp[0], lp[1], lp[2], lp[3]);
            if (mode == 3) {
                *reinterpret_cast<uint4*>(C2hi + moff) = make_uint4(wh[0], wh[1], wh[2], wh[3]);
                *reinterpret_cast<uint4*>(C2lo + moff) = make_uint4(wl[0], wl[1], wl[2], wl[3]);
            }
        }
    }
}

// ---------------------------------------------------------------------------
__global__ __launch_bounds__(256)
void split_x_kernel(const float* __restrict__ x,
                    __nv_bfloat16* __restrict__ xhi, __nv_bfloat16* __restrict__ xlo) {
    int row = blockIdx.x * 8 + (threadIdx.x >> 5);
    int lane = threadIdx.x & 31;
    const float* src = x + (size_t)row * MMSP;
    __nv_bfloat16* dh = xhi + (size_t)row * KPAD;
    __nv_bfloat16* dl = xlo + (size_t)row * KPAD;
#pragma unroll
    for (int m = lane; m < KPAD; m += 32) {
        float v = (m < MMSP) ? src[m] : 0.f;
        __nv_bfloat16 h = __float2bfloat16(v);
        dh[m] = h;
        dl[m] = __float2bfloat16(v - __bfloat162float(h));
    }
}

__global__ void rowsum_norm_kernel(const float* __restrict__ x,
                                   float* __restrict__ s, float* __restrict__ nrm) {
    int b = blockIdx.x, c = threadIdx.x;
    const float* p = x + ((size_t)b * CCH + c) * MMSP;
    float sum = 0.f, q = 0.f;
#pragma unroll 4
    for (int m = 0; m < MMSP; ++m) { float v = p[m]; sum += v; q += v * v; }
    s[b * CCH + c] = sum;
    float part = q - sum * sum * (1.0f / 196.0f);
    __shared__ float sh[8];
#pragma unroll
    for (int o = 16; o > 0; o >>= 1) part += __shfl_down_sync(0xffffffffu, part, o);
    if ((c & 31) == 0) sh[c >> 5] = part;
    __syncthreads();
    if (c < 8) {
        float w = sh[c];
#pragma unroll
        for (int o = 4; o > 0; o >>= 1) w += __shfl_down_sync(0xffu, w, o);
        if (c == 0) nrm[b] = w * (1.0f / 196.0f);
    }
}

__global__ void finish_kernel(const float* __restrict__ part,
                              const float* __restrict__ bias, float* __restrict__ out) {
    int i = blockIdx.x * blockDim.x + threadIdx.x;
    int b = i >> 1, k = i & 1;
    out[i] = bias[k] + part[(b * 3 + 0) * 2 + k]
                     + part[(b * 3 + 1) * 2 + k]
                     + part[(b * 3 + 2) * 2 + k];
}

// ---------------------------------------------------------------------------
struct Planes {
    __nv_bfloat16 *Xh, *Xl, *Ph, *Pl, *Qh, *Ql, *Rh, *Rl, *Sh, *Sl, *Th, *Tl;
    float *part, *sums, *nrm;
};

static void run_chain(cudaStream_t st, int bbase, const Planes& p,
                      const float* fc_w) {
    dim3 g1(3, QTR);
    dim3 g2(6, QTR);
    const long strX = (long)CCH * KPAD;
    const long strM = (long)MAT;
    const __nv_bfloat16* nbp = 0;
    __nv_bfloat16* nbo = 0;

    gemm_tc<<<g1, 256, SMEM_TOTAL, st>>>(p.Xh, p.Xl, p.Xh, p.Xl, p.Ph, p.Pl, p.Qh, p.Ql,
                                         nbp, nbp, nbp, nbp, nbo, nbo, (const float*)0, (float*)0,
                                         KPAD, strX, KPAD, 3, bbase, p.nrm, p.sums);
    gemm_tc<<<g1, 256, SMEM_TOTAL, st>>>(p.Ph, p.Pl, p.Qh, p.Ql, p.Rh, p.Rl, nbo, nbo,
                                         nbp, nbp, nbp, nbp, nbo, nbo, (const float*)0, (float*)0,
                                         CCH, strM, CCH, 0, bbase, p.nrm, 0);
    gemm_tc<<<g1, 256, SMEM_TOTAL, st>>>(p.Qh, p.Ql, p.Rh, p.Rl, p.Sh, p.Sl, nbo, nbo,
                                         nbp, nbp, nbp, nbp, nbo, nbo, (const float*)0, (float*)0,
                                         CCH, strM, CCH, 1, bbase, p.nrm, 0);
    gemm_tc<<<g2, 256, SMEM_TOTAL, st>>>(p.Rh, p.Rl, p.Sh, p.Sl, p.Th, p.Tl, nbo, nbo,
                                         p.Sh, p.Sl, p.Qh, p.Ql, p.Ph, p.Pl, (const float*)0, (float*)0,
                                         CCH, strM, CCH, 0, bbase, p.nrm, 0);
    gemm_tc<<<g1, 256, SMEM_TOTAL, st>>>(p.Ph, p.Pl, p.Th, p.Tl, p.Sh, p.Sl, nbo, nbo,
                                         nbp, nbp, nbp, nbp, nbo, nbo, (const float*)0, (float*)0,
                                         CCH, strM, CCH, 1, bbase, p.nrm, 0);
    gemm_tc<<<g2, 256, SMEM_TOTAL, st>>>(p.Th, p.Tl, p.Sh, p.Sl, p.Qh, p.Ql, nbo, nbo,
                                         p.Sh, p.Sl, p.Ph, p.Pl, p.Rh, p.Rl, (const float*)0, (float*)0,
                                         CCH, strM, CCH, 0, bbase, p.nrm, 0);
    gemm_tc<<<g1, 256, SMEM_TOTAL, st>>>(p.Rh, p.Rl, p.Qh, p.Ql, p.Sh, p.Sl, nbo, nbo,
                                         nbp, nbp, nbp, nbp, nbo, nbo, (const float*)0, (float*)0,
                                         CCH, strM, CCH, 1, bbase, p.nrm, 0);
    gemm_tc<<<g2, 256, SMEM_TOTAL, st>>>(p.Qh, p.Ql, p.Sh, p.Sl, p.Th, p.Tl, nbo, nbo,
                                         p.Sh, p.Sl, p.Rh, p.Rl, p.Ph, p.Pl, (const float*)0, (float*)0,
                                         CCH, strM, CCH, 0, bbase, p.nrm, 0);
    gemm_tc<<<g1, 256, SMEM_TOTAL, st>>>(p.Ph, p.Pl, p.Th, p.Tl, p.Sh, p.Sl, nbo, nbo,
                                         nbp, nbp, nbp, nbp, nbo, nbo, (const float*)0, (float*)0,
                                         CCH, strM, CCH, 1, bbase, p.nrm, 0);
    gemm_tc<<<g1, 256, SMEM_TOTAL, st>>>(p.Th, p.Tl, p.Sh, p.Sl, nbo, nbo, nbo, nbo,
                                         nbp, nbp, nbp, nbp, nbo, nbo, fc_w, p.part,
                                         CCH, strM, CCH, 2, bbase, p.nrm, 0);
}

extern "C" void kernel_launch(void* const* d_in, const int* in_sizes, int n_in,
                              void* d_out, int out_size) {
    const float* x    = (const float*)d_in[0];
    const float* fc_w = (const float*)d_in[1];
    const float* fc_b = (const float*)d_in[2];
    float* out        = (float*)d_out;

    Planes p;
    cudaGetSymbolAddress((void**)&p.Xh, g_Xhi); cudaGetSymbolAddress((void**)&p.Xl, g_Xlo);
    cudaGetSymbolAddress((void**)&p.Ph, g_Phi); cudaGetSymbolAddress((void**)&p.Pl, g_Plo);
    cudaGetSymbolAddress((void**)&p.Qh, g_Qhi); cudaGetSymbolAddress((void**)&p.Ql, g_Qlo);
    cudaGetSymbolAddress((void**)&p.Rh, g_Rhi); cudaGetSymbolAddress((void**)&p.Rl, g_Rlo);
    cudaGetSymbolAddress((void**)&p.Sh, g_Shi); cudaGetSymbolAddress((void**)&p.Sl, g_Slo);
    cudaGetSymbolAddress((void**)&p.Th, g_Thi); cudaGetSymbolAddress((void**)&p.Tl, g_Tlo);
    cudaGetSymbolAddress((void**)&p.part, g_part);
    cudaGetSymbolAddress((void**)&p.sums, g_sums);
    cudaGetSymbolAddress((void**)&p.nrm, g_norm);

    cudaFuncSetAttribute(gemm_tc, cudaFuncAttributeMaxDynamicSharedMemorySize, SMEM_TOTAL);

    rowsum_norm_kernel<<<BATCH, CCH>>>(x, p.sums, p.nrm);
    split_x_kernel<<<BATCH * CCH / 8, 256>>>(x, p.Xh, p.Xl);

    cudaStream_t s[NSTREAMS - 1];
    cudaEvent_t evFork, evJoin[NSTREAMS - 1];
    for (int i = 0; i < NSTREAMS - 1; ++i)
        cudaStreamCreateWithFlags(&s[i], cudaStreamNonBlocking);
    cudaEventCreateWithFlags(&evFork, cudaEventDisableTiming);
    for (int i = 0; i < NSTREAMS - 1; ++i)
        cudaEventCreateWithFlags(&evJoin[i], cudaEventDisableTiming);

    cudaEventRecord(evFork, 0);
    for (int i = 0; i < NSTREAMS - 1; ++i)
        cudaStreamWaitEvent(s[i], evFork, 0);

    run_chain((cudaStream_t)0, 0 * QTR, p, fc_w);
    for (int i = 0; i < NSTREAMS - 1; ++i)
        run_chain(s[i], (i + 1) * QTR, p, fc_w);

    for (int i = 0; i < NSTREAMS - 1; ++i) {
        cudaEventRecord(evJoin[i], s[i]);
        cudaStreamWaitEvent((cudaStream_t)0, evJoin[i], 0);
    }

    finish_kernel<<<2, 256>>>(p.part, fc_b, out);

    for (int i = 0; i < NSTREAMS - 1; ++i) {
        cudaStreamDestroy(s[i]);
        cudaEventDestroy(evJoin[i]);
    }
    cudaEventDestroy(evFork);
}

// round 14
// speedup vs baseline: 1.0542x; 1.0542x over previous
#include <cuda_runtime.h>
#include <cuda_bf16.h>
#include <math.h>
#include <stdint.h>

#define BATCH 256
#define QTR   64
#define NSTREAMS 4
#define CCH   256
#define MMSP  196
#define KPAD  224
#define DTRI  32896
#define MAT   65536

// bf16 hi/lo planes
__device__ __nv_bfloat16 g_Xhi[(size_t)BATCH * CCH * KPAD];
__device__ __nv_bfloat16 g_Xlo[(size_t)BATCH * CCH * KPAD];
__device__ __nv_bfloat16 g_Phi[(size_t)BATCH * MAT];
__device__ __nv_bfloat16 g_Plo[(size_t)BATCH * MAT];
__device__ __nv_bfloat16 g_Qhi[(size_t)BATCH * MAT];
__device__ __nv_bfloat16 g_Qlo[(size_t)BATCH * MAT];
__device__ __nv_bfloat16 g_Rhi[(size_t)BATCH * MAT];
__device__ __nv_bfloat16 g_Rlo[(size_t)BATCH * MAT];
__device__ __nv_bfloat16 g_Shi[(size_t)BATCH * MAT];
__device__ __nv_bfloat16 g_Slo[(size_t)BATCH * MAT];
__device__ __nv_bfloat16 g_Thi[(size_t)BATCH * MAT];
__device__ __nv_bfloat16 g_Tlo[(size_t)BATCH * MAT];
__device__ float g_part[BATCH * 3 * 2];
__device__ float g_sums[BATCH * CCH];
__device__ float g_norm[BATCH];

// ---------------------------------------------------------------------------
__device__ __forceinline__ uint32_t smem_u32(const void* p) {
    uint32_t a;
    asm("{ .reg .u64 t; cvta.to.shared.u64 t, %1; cvt.u32.u64 %0, t; }" : "=r"(a) : "l"(p));
    return a;
}
__device__ __forceinline__ void ldsm4(uint32_t addr, uint32_t* r) {
    asm volatile("ldmatrix.sync.aligned.m8n8.x4.shared.b16 {%0,%1,%2,%3}, [%4];"
        : "=r"(r[0]), "=r"(r[1]), "=r"(r[2]), "=r"(r[3]) : "r"(addr));
}
// NOTE: non-volatile — pure register op; ptxas schedules it freely on true deps.
__device__ __forceinline__ void mma_bf16(float* d, const uint32_t* a,
                                         uint32_t b0, uint32_t b1) {
    asm("mma.sync.aligned.m16n8k16.row.col.f32.bf16.bf16.f32 "
        "{%0,%1,%2,%3}, {%4,%5,%6,%7}, {%8,%9}, {%0,%1,%2,%3};"
        : "+f"(d[0]), "+f"(d[1]), "+f"(d[2]), "+f"(d[3])
        : "r"(a[0]), "r"(a[1]), "r"(a[2]), "r"(a[3]), "r"(b0), "r"(b1));
}
__device__ __forceinline__ void cp16(uint32_t dst, const void* src) {
    asm volatile("cp.async.cg.shared.global [%0], [%1], 16;" :: "r"(dst), "l"(src));
}
#define CP_COMMIT()  asm volatile("cp.async.commit_group;" ::: "memory")
#define CP_WAIT(N)   asm volatile("cp.async.wait_group %0;" :: "n"(N) : "memory")

#define ABUF(b)   ((b) * 32768)
#define BBUF(b)   ((b) * 32768 + 16384)
#define SMEM_TOTAL (3 * 32768)
#define STG_LDS   132

__device__ __forceinline__ void split_pack(float a, float b, uint32_t& hi, uint32_t& lo) {
    __nv_bfloat16 ha = __float2bfloat16(a);
    __nv_bfloat16 hb = __float2bfloat16(b);
    __nv_bfloat162 hh; hh.x = ha; hh.y = hb;
    __nv_bfloat162 ll;
    ll.x = __float2bfloat16(a - __bfloat162float(ha));
    ll.y = __float2bfloat16(b - __bfloat162float(hb));
    hi = *reinterpret_cast<uint32_t*>(&hh);
    lo = *reinterpret_cast<uint32_t*>(&ll);
}

// ---------------------------------------------------------------------------
// Symmetric-output batched GEMM on bf16 hi/lo planes, 3-product split.
// bx=0 -> (0,0); 1 -> (0,128) (+ smem-transposed mirror); 2 -> (128,128).
// bx in [3,6): second GEMM of a fused pair (mode forced 0).
// modes: 0 planes; 1 TI planes; 2 fused triu-FC partials; 3 cov (Ahat + ZY)
// b = blockIdx.y + bbase (multi-stream batch slices)
// ---------------------------------------------------------------------------
__global__ __launch_bounds__(256, 2)
void gemm_tc(const __nv_bfloat16* __restrict__ Ahi, const __nv_bfloat16* __restrict__ Alo,
             const __nv_bfloat16* __restrict__ Bhi, const __nv_bfloat16* __restrict__ Blo,
             __nv_bfloat16* __restrict__ Chi, __nv_bfloat16* __restrict__ Clo,
             __nv_bfloat16* __restrict__ C2hi, __nv_bfloat16* __restrict__ C2lo,
             const __nv_bfloat16* A2hi, const __nv_bfloat16* A2lo,
             const __nv_bfloat16* B2hi, const __nv_bfloat16* B2lo,
             __nv_bfloat16* D2hi, __nv_bfloat16* D2lo,
             const float* __restrict__ fcw, float* __restrict__ part,
             int ldk, long strAB, int K, int mode, int bbase,
             const float* __restrict__ norm, const float* __restrict__ sums) {
    extern __shared__ char smem[];
    const uint32_t smb = smem_u32(smem);

    const int tid  = threadIdx.x;
    const int wid  = tid >> 5;
    const int lane = tid & 31;
    const int wm = wid >> 2;
    const int wn = wid & 3;
    const int g  = lane >> 2;
    const int t  = lane & 3;

    int bx = blockIdx.x;
    const int b = blockIdx.y + bbase;

    const __nv_bfloat16 *pAh = Ahi, *pAl = Alo, *pBh = Bhi, *pBl = Blo;
    __nv_bfloat16 *pCh = Chi, *pCl = Clo;
    if (bx >= 3) {
        bx -= 3;
        pAh = A2hi; pAl = A2lo; pBh = B2hi; pBl = B2lo;
        pCh = D2hi; pCl = D2lo;
        mode = 0;
    }
    const int m0 = (bx == 2) ? 128 : 0;
    const int n0 = (bx >= 1) ? 128 : 0;
    const bool offdiag = (m0 != n0);

    const __nv_bfloat16* Abh = pAh + (size_t)b * strAB + (size_t)m0 * ldk;
    const __nv_bfloat16* Abl = pAl + (size_t)b * strAB + (size_t)m0 * ldk;
    const __nv_bfloat16* Bbh = pBh + (size_t)b * strAB + (size_t)n0 * ldk;
    const __nv_bfloat16* Bbl = pBl + (size_t)b * strAB + (size_t)n0 * ldk;

    const int r0c = (tid + 0)   >> 2, c0c = tid & 3;
    const int r1c = (tid + 256) >> 2;
    const int nch = K >> 5;

    float acc[4][4][4];
#pragma unroll
    for (int i = 0; i < 4; ++i)
#pragma unroll
        for (int j = 0; j < 4; ++j)
#pragma unroll
            for (int k = 0; k < 4; ++k) acc[i][j][k] = 0.f;

    auto issue = [&](int ch, int buf) {
        int col = (ch << 5) + c0c * 8;
        uint32_t swh0 = (uint32_t)((c0c       ^ (r0c & 7)) << 4);
        uint32_t swl0 = (uint32_t)(((4 + c0c) ^ (r0c & 7)) << 4);
        uint32_t swh1 = (uint32_t)((c0c       ^ (r1c & 7)) << 4);
        uint32_t swl1 = (uint32_t)(((4 + c0c) ^ (r1c & 7)) << 4);
        uint32_t dA0 = smb + ABUF(buf) + r0c * 128;
        uint32_t dB0 = smb + BBUF(buf) + r0c * 128;
        uint32_t dA1 = smb + ABUF(buf) + r1c * 128;
        uint32_t dB1 = smb + BBUF(buf) + r1c * 128;
        cp16(dA0 + swh0, Abh + (size_t)r0c * ldk + col);
        cp16(dA0 + swl0, Abl + (size_t)r0c * ldk + col);
        cp16(dB0 + swh0, Bbh + (size_t)r0c * ldk + col);
        cp16(dB0 + swl0, Bbl + (size_t)r0c * ldk + col);
        cp16(dA1 + swh1, Abh + (size_t)r1c * ldk + col);
        cp16(dA1 + swl1, Abl + (size_t)r1c * ldk + col);
        cp16(dB1 + swh1, Bbh + (size_t)r1c * ldk + col);
        cp16(dB1 + swl1, Bbl + (size_t)r1c * ldk + col);
    };

    issue(0, 0); CP_COMMIT();
    if (nch > 1) { issue(1, 1); CP_COMMIT(); }

    for (int ch = 0; ch < nch; ++ch) {
        if (ch + 1 < nch) { CP_WAIT(1); } else { CP_WAIT(0); }
        __syncthreads();
        if (ch + 2 < nch) { issue(ch + 2, (ch + 2) % 3); CP_COMMIT(); }

        const int buf = ch % 3;
        const uint32_t smA = smb + ABUF(buf);
        const uint32_t smB = smb + BBUF(buf);

#pragma unroll
        for (int ks = 0; ks < 2; ++ks) {
            uint32_t ah[4][4], al[4][4];
#pragma unroll
            for (int mt = 0; mt < 4; ++mt) {
                int r = wm * 64 + mt * 16 + (lane & 15);
                int cb = ks * 2 + (lane >> 4);
                ldsm4(smA + r * 128 + ((cb       ^ (r & 7)) << 4), ah[mt]);
                ldsm4(smA + r * 128 + (((4 + cb) ^ (r & 7)) << 4), al[mt]);
            }
            uint32_t bh[2][4], bl[2][4];
#pragma unroll
            for (int bt = 0; bt < 2; ++bt) {
                int r = wn * 32 + bt * 16 + ((lane >> 4) << 3) + (lane & 7);
                int cb = ks * 2 + ((lane >> 3) & 1);
                ldsm4(smB + r * 128 + ((cb       ^ (r & 7)) << 4), bh[bt]);
                ldsm4(smB + r * 128 + (((4 + cb) ^ (r & 7)) << 4), bl[bt]);
            }
#pragma unroll
            for (int mt = 0; mt < 4; ++mt)
#pragma unroll
                for (int nt = 0; nt < 4; ++nt) {
                    const uint32_t* bhp = &bh[nt >> 1][(nt & 1) * 2];
                    mma_bf16(acc[mt][nt], ah[mt], bhp[0], bhp[1]);
                }
#pragma unroll
            for (int mt = 0; mt < 4; ++mt)
#pragma unroll
                for (int nt = 0; nt < 4; ++nt) {
                    const uint32_t* blp = &bl[nt >> 1][(nt & 1) * 2];
                    mma_bf16(acc[mt][nt], ah[mt], blp[0], blp[1]);
                }
#pragma unroll
            for (int mt = 0; mt < 4; ++mt)
#pragma unroll
                for (int nt = 0; nt < 4; ++nt) {
                    const uint32_t* bhp = &bh[nt >> 1][(nt & 1) * 2];
                    mma_bf16(acc[mt][nt], al[mt], bhp[0], bhp[1]);
                }
        }
    }

    const size_t cbase = (size_t)b * MAT;

    if (mode == 2) {
        float sc = sqrtf(norm[b]);
        float f0 = 0.f, f1 = 0.f;
#pragma unroll
        for (int mt = 0; mt < 4; ++mt) {
            int r0 = m0 + wm * 64 + mt * 16 + g;
#pragma unroll
            for (int nt = 0; nt < 4; ++nt) {
                int c0 = n0 + wn * 32 + nt * 8 + 2 * t;
                float* d = acc[mt][nt];
#pragma unroll
                for (int half = 0; half < 2; ++half) {
                    int gi = r0 + half * 8;
                    float v0 = d[half * 2 + 0] * sc;
                    float v1 = d[half * 2 + 1] * sc;
                    int tt = gi * CCH - ((gi * (gi + 1)) >> 1) + c0;
                    if (offdiag || c0 >= gi) {
                        f0 += v0 * __ldg(fcw + tt);
                        f1 += v0 * __ldg(fcw + DTRI + tt);
                    }
                    if (offdiag || c0 + 1 >= gi) {
                        f0 += v1 * __ldg(fcw + tt + 1);
                        f1 += v1 * __ldg(fcw + DTRI + tt + 1);
                    }
                }
            }
        }
        __syncthreads();
        float* red = reinterpret_cast<float*>(smem);
        red[tid] = f0; red[256 + tid] = f1;
        __syncthreads();
        for (int off = 128; off > 0; off >>= 1) {
            if (tid < off) { red[tid] += red[tid + off]; red[256 + tid] += red[256 + tid + off]; }
            __syncthreads();
        }
        if (tid == 0) {
            part[(b * 3 + bx) * 2 + 0] = red[0];
            part[(b * 3 + bx) * 2 + 1] = red[256];
        }
        return;
    }

    float invMn = 0.0f;
    const float* sb = 0;
    if (mode == 3) {
        invMn = 1.0f / (196.0f * norm[b]);
        sb = sums + b * CCH;
    }

    __syncthreads();
    float* stg = reinterpret_cast<float*>(smem);

#pragma unroll
    for (int mt = 0; mt < 4; ++mt) {
        int r0 = m0 + wm * 64 + mt * 16 + g;
#pragma unroll
        for (int nt = 0; nt < 4; ++nt) {
            int c0 = n0 + wn * 32 + nt * 8 + 2 * t;
            float* d = acc[mt][nt];
#pragma unroll
            for (int half = 0; half < 2; ++half) {
                int gi = r0 + half * 8;
                float v0 = d[half * 2 + 0];
                float v1 = d[half * 2 + 1];
                size_t off = cbase + (size_t)gi * CCH + c0;
                if (mode == 1) {
                    v0 = (gi == c0     ? 1.5f : 0.0f) - 0.5f * v0;
                    v1 = (gi == c0 + 1 ? 1.5f : 0.0f) - 0.5f * v1;
                } else if (mode == 3) {
                    float si = sb[gi] * (1.0f / 196.0f);
                    v0 = (v0 - si * sb[c0])     * invMn;
                    v1 = (v1 - si * sb[c0 + 1]) * invMn;
                    float w0 = (gi == c0     ? 1.5f : 0.0f) - 0.5f * v0;
                    float w1 = (gi == c0 + 1 ? 1.5f : 0.0f) - 0.5f * v1;
                    uint32_t whi, wlo;
                    split_pack(w0, w1, whi, wlo);
                    *reinterpret_cast<uint32_t*>(C2hi + off) = whi;
                    *reinterpret_cast<uint32_t*>(C2lo + off) = wlo;
                }
                uint32_t hi, lo;
                split_pack(v0, v1, hi, lo);
                *reinterpret_cast<uint32_t*>(pCh + off) = hi;
                *reinterpret_cast<uint32_t*>(pCl + off) = lo;
                if (offdiag) {
                    int lr = gi - m0, lc = c0 - n0;
                    stg[lr * STG_LDS + lc]     = v0;
                    stg[lr * STG_LDS + lc + 1] = v1;
                }
            }
        }
    }

    if (offdiag) {
        __syncthreads();
        const int j  = tid & 127;
        const int ib = tid >> 7;
#pragma unroll
        for (int s = 0; s < 8; ++s) {
            int i0 = ib * 64 + s * 8;
            uint32_t hp[4], lp[4], wh[4], wl[4];
#pragma unroll
            for (int k = 0; k < 4; ++k) {
                float a = stg[(i0 + 2 * k)     * STG_LDS + j];
                float c = stg[(i0 + 2 * k + 1) * STG_LDS + j];
                split_pack(a, c, hp[k], lp[k]);
                if (mode == 3) split_pack(-0.5f * a, -0.5f * c, wh[k], wl[k]);
            }
            size_t moff = cbase + (size_t)(n0 + j) * CCH + (m0 + i0);
            *reinterpret_cast<uint4*>(pCh + moff) = make_uint4(hp[0], hp[1], hp[2], hp[3]);
            *reinterpret_cast<uint4*>(pCl + moff) = make_uint4(lp[0], lp[1], lp[2], lp[3]);
            if (mode == 3) {
                *reinterpret_cast<uint4*>(C2hi + moff) = make_uint4(wh[0], wh[1], wh[2], wh[3]);
                *reinterpret_cast<uint4*>(C2lo + moff) = make_uint4(wl[0], wl[1], wl[2], wl[3]);
            }
        }
    }
}

// ---------------------------------------------------------------------------
__global__ __launch_bounds__(256)
void split_x_kernel(const float* __restrict__ x,
                    __nv_bfloat16* __restrict__ xhi, __nv_bfloat16* __restrict__ xlo) {
    int row = blockIdx.x * 8 + (threadIdx.x >> 5);
    int lane = threadIdx.x & 31;
    const float* src = x + (size_t)row * MMSP;
    __nv_bfloat16* dh = xhi + (size_t)row * KPAD;
    __nv_bfloat16* dl = xlo + (size_t)row * KPAD;
#pragma unroll
    for (int m = lane; m < KPAD; m += 32) {
        float v = (m < MMSP) ? src[m] : 0.f;
        __nv_bfloat16 h = __float2bfloat16(v);
        dh[m] = h;
        dl[m] = __float2bfloat16(v - __bfloat162float(h));
    }
}

__global__ void rowsum_norm_kernel(const float* __restrict__ x,
                                   float* __restrict__ s, float* __restrict__ nrm) {
    int b = blockIdx.x, c = threadIdx.x;
    const float* p = x + ((size_t)b * CCH + c) * MMSP;
    float sum = 0.f, q = 0.f;
#pragma unroll 4
    for (int m = 0; m < MMSP; ++m) { float v = p[m]; sum += v; q += v * v; }
    s[b * CCH + c] = sum;
    float part = q - sum * sum * (1.0f / 196.0f);
    __shared__ float sh[8];
#pragma unroll
    for (int o = 16; o > 0; o >>= 1) part += __shfl_down_sync(0xffffffffu, part, o);
    if ((c & 31) == 0) sh[c >> 5] = part;
    __syncthreads();
    if (c < 8) {
        float w = sh[c];
#pragma unroll
        for (int o = 4; o > 0; o >>= 1) w += __shfl_down_sync(0xffu, w, o);
        if (c == 0) nrm[b] = w * (1.0f / 196.0f);
    }
}

__global__ void finish_kernel(const float* __restrict__ part,
                              const float* __restrict__ bias, float* __restrict__ out) {
    int i = blockIdx.x * blockDim.x + threadIdx.x;
    int b = i >> 1, k = i & 1;
    out[i] = bias[k] + part[(b * 3 + 0) * 2 + k]
                     + part[(b * 3 + 1) * 2 + k]
                     + part[(b * 3 + 2) * 2 + k];
}

// ---------------------------------------------------------------------------
struct Planes {
    __nv_bfloat16 *Xh, *Xl, *Ph, *Pl, *Qh, *Ql, *Rh, *Rl, *Sh, *Sl, *Th, *Tl;
    float *part, *sums, *nrm;
};

static void run_chain(cudaStream_t st, int bbase, const Planes& p,
                      const float* fc_w) {
    dim3 g1(3, QTR);
    dim3 g2(6, QTR);
    const long strX = (long)CCH * KPAD;
    const long strM = (long)MAT;
    const __nv_bfloat16* nbp = 0;
    __nv_bfloat16* nbo = 0;

    gemm_tc<<<g1, 256, SMEM_TOTAL, st>>>(p.Xh, p.Xl, p.Xh, p.Xl, p.Ph, p.Pl, p.Qh, p.Ql,
                                         nbp, nbp, nbp, nbp, nbo, nbo, (const float*)0, (float*)0,
                                         KPAD, strX, KPAD, 3, bbase, p.nrm, p.sums);
    gemm_tc<<<g1, 256, SMEM_TOTAL, st>>>(p.Ph, p.Pl, p.Qh, p.Ql, p.Rh, p.Rl, nbo, nbo,
                                         nbp, nbp, nbp, nbp, nbo, nbo, (const float*)0, (float*)0,
                                         CCH, strM, CCH, 0, bbase, p.nrm, 0);
    gemm_tc<<<g1, 256, SMEM_TOTAL, st>>>(p.Qh, p.Ql, p.Rh, p.Rl, p.Sh, p.Sl, nbo, nbo,
                                         nbp, nbp, nbp, nbp, nbo, nbo, (const float*)0, (float*)0,
                                         CCH, strM, CCH, 1, bbase, p.nrm, 0);
    gemm_tc<<<g2, 256, SMEM_TOTAL, st>>>(p.Rh, p.Rl, p.Sh, p.Sl, p.Th, p.Tl, nbo, nbo,
                                         p.Sh, p.Sl, p.Qh, p.Ql, p.Ph, p.Pl, (const float*)0, (float*)0,
                                         CCH, strM, CCH, 0, bbase, p.nrm, 0);
    gemm_tc<<<g1, 256, SMEM_TOTAL, st>>>(p.Ph, p.Pl, p.Th, p.Tl, p.Sh, p.Sl, nbo, nbo,
                                         nbp, nbp, nbp, nbp, nbo, nbo, (const float*)0, (float*)0,
                                         CCH, strM, CCH, 1, bbase, p.nrm, 0);
    gemm_tc<<<g2, 256, SMEM_TOTAL, st>>>(p.Th, p.Tl, p.Sh, p.Sl, p.Qh, p.Ql, nbo, nbo,
                                         p.Sh, p.Sl, p.Ph, p.Pl, p.Rh, p.Rl, (const float*)0, (float*)0,
                                         CCH, strM, CCH, 0, bbase, p.nrm, 0);
    gemm_tc<<<g1, 256, SMEM_TOTAL, st>>>(p.Rh, p.Rl, p.Qh, p.Ql, p.Sh, p.Sl, nbo, nbo,
                                         nbp, nbp, nbp, nbp, nbo, nbo, (const float*)0, (float*)0,
                                         CCH, strM, CCH, 1, bbase, p.nrm, 0);
    gemm_tc<<<g2, 256, SMEM_TOTAL, st>>>(p.Qh, p.Ql, p.Sh, p.Sl, p.Th, p.Tl, nbo, nbo,
                                         p.Sh, p.Sl, p.Rh, p.Rl, p.Ph, p.Pl, (const float*)0, (float*)0,
                                         CCH, strM, CCH, 0, bbase, p.nrm, 0);
    gemm_tc<<<g1, 256, SMEM_TOTAL, st>>>(p.Ph, p.Pl, p.Th, p.Tl, p.Sh, p.Sl, nbo, nbo,
                                         nbp, nbp, nbp, nbp, nbo, nbo, (const float*)0, (float*)0,
                                         CCH, strM, CCH, 1, bbase, p.nrm, 0);
    gemm_tc<<<g1, 256, SMEM_TOTAL, st>>>(p.Th, p.Tl, p.Sh, p.Sl, nbo, nbo, nbo, nbo,
                                         nbp, nbp, nbp, nbp, nbo, nbo, fc_w, p.part,
                                         CCH, strM, CCH, 2, bbase, p.nrm, 0);
}

extern "C" void kernel_launch(void* const* d_in, const int* in_sizes, int n_in,
                              void* d_out, int out_size) {
    const float* x    = (const float*)d_in[0];
    const float* fc_w = (const float*)d_in[1];
    const float* fc_b = (const float*)d_in[2];
    float* out        = (float*)d_out;

    Planes p;
    cudaGetSymbolAddress((void**)&p.Xh, g_Xhi); cudaGetSymbolAddress((void**)&p.Xl, g_Xlo);
    cudaGetSymbolAddress((void**)&p.Ph, g_Phi); cudaGetSymbolAddress((void**)&p.Pl, g_Plo);
    cudaGetSymbolAddress((void**)&p.Qh, g_Qhi); cudaGetSymbolAddress((void**)&p.Ql, g_Qlo);
    cudaGetSymbolAddress((void**)&p.Rh, g_Rhi); cudaGetSymbolAddress((void**)&p.Rl, g_Rlo);
    cudaGetSymbolAddress((void**)&p.Sh, g_Shi); cudaGetSymbolAddress((void**)&p.Sl, g_Slo);
    cudaGetSymbolAddress((void**)&p.Th, g_Thi); cudaGetSymbolAddress((void**)&p.Tl, g_Tlo);
    cudaGetSymbolAddress((void**)&p.part, g_part);
    cudaGetSymbolAddress((void**)&p.sums, g_sums);
    cudaGetSymbolAddress((void**)&p.nrm, g_norm);

    cudaFuncSetAttribute(gemm_tc, cudaFuncAttributeMaxDynamicSharedMemorySize, SMEM_TOTAL);

    rowsum_norm_kernel<<<BATCH, CCH>>>(x, p.sums, p.nrm);
    split_x_kernel<<<BATCH * CCH / 8, 256>>>(x, p.Xh, p.Xl);

    cudaStream_t s[NSTREAMS - 1];
    cudaEvent_t evFork, evJoin[NSTREAMS - 1];
    for (int i = 0; i < NSTREAMS - 1; ++i)
        cudaStreamCreateWithFlags(&s[i], cudaStreamNonBlocking);
    cudaEventCreateWithFlags(&evFork, cudaEventDisableTiming);
    for (int i = 0; i < NSTREAMS - 1; ++i)
        cudaEventCreateWithFlags(&evJoin[i], cudaEventDisableTiming);

    cudaEventRecord(evFork, 0);
    for (int i = 0; i < NSTREAMS - 1; ++i)
        cudaStreamWaitEvent(s[i], evFork, 0);

    run_chain((cudaStream_t)0, 0 * QTR, p, fc_w);
    for (int i = 0; i < NSTREAMS - 1; ++i)
        run_chain(s[i], (i + 1) * QTR, p, fc_w);

    for (int i = 0; i < NSTREAMS - 1; ++i) {
        cudaEventRecord(evJoin[i], s[i]);
        cudaStreamWaitEvent((cudaStream_t)0, evJoin[i], 0);
    }

    finish_kernel<<<2, 256>>>(p.part, fc_b, out);

    for (int i = 0; i < NSTREAMS - 1; ++i) {
        cudaStreamDestroy(s[i]);
        cudaEventDestroy(evJoin[i]);
    }
    cudaEventDestroy(evFork);
}

// round 15
// speedup vs baseline: 1.0618x; 1.0072x over previous
#include <cuda_runtime.h>
#include <cuda_bf16.h>
#include <math.h>
#include <stdint.h>

#define BATCH 256
#define QTR   64
#define NSTREAMS 4
#define CCH   256
#define MMSP  196
#define KPAD  224
#define DTRI  32896
#define MAT   65536

// bf16 hi/lo planes
__device__ __nv_bfloat16 g_Xhi[(size_t)BATCH * CCH * KPAD];
__device__ __nv_bfloat16 g_Xlo[(size_t)BATCH * CCH * KPAD];
__device__ __nv_bfloat16 g_Phi[(size_t)BATCH * MAT];
__device__ __nv_bfloat16 g_Plo[(size_t)BATCH * MAT];
__device__ __nv_bfloat16 g_Qhi[(size_t)BATCH * MAT];
__device__ __nv_bfloat16 g_Qlo[(size_t)BATCH * MAT];
__device__ __nv_bfloat16 g_Rhi[(size_t)BATCH * MAT];
__device__ __nv_bfloat16 g_Rlo[(size_t)BATCH * MAT];
__device__ __nv_bfloat16 g_Shi[(size_t)BATCH * MAT];
__device__ __nv_bfloat16 g_Slo[(size_t)BATCH * MAT];
__device__ __nv_bfloat16 g_Thi[(size_t)BATCH * MAT];
__device__ __nv_bfloat16 g_Tlo[(size_t)BATCH * MAT];
__device__ float g_part[BATCH * 3 * 2];
__device__ float g_sums[BATCH * CCH];
__device__ float g_norm[BATCH];

// ---------------------------------------------------------------------------
__device__ __forceinline__ uint32_t smem_u32(const void* p) {
    uint32_t a;
    asm("{ .reg .u64 t; cvta.to.shared.u64 t, %1; cvt.u32.u64 %0, t; }" : "=r"(a) : "l"(p));
    return a;
}
__device__ __forceinline__ void ldsm4(uint32_t addr, uint32_t* r) {
    asm volatile("ldmatrix.sync.aligned.m8n8.x4.shared.b16 {%0,%1,%2,%3}, [%4];"
        : "=r"(r[0]), "=r"(r[1]), "=r"(r[2]), "=r"(r[3]) : "r"(addr));
}
__device__ __forceinline__ void mma_bf16(float* d, const uint32_t* a,
                                         uint32_t b0, uint32_t b1) {
    asm volatile("mma.sync.aligned.m16n8k16.row.col.f32.bf16.bf16.f32 "
                 "{%0,%1,%2,%3}, {%4,%5,%6,%7}, {%8,%9}, {%0,%1,%2,%3};"
        : "+f"(d[0]), "+f"(d[1]), "+f"(d[2]), "+f"(d[3])
        : "r"(a[0]), "r"(a[1]), "r"(a[2]), "r"(a[3]), "r"(b0), "r"(b1));
}
__device__ __forceinline__ void cp16(uint32_t dst, const void* src) {
    asm volatile("cp.async.cg.shared.global [%0], [%1], 16;" :: "r"(dst), "l"(src));
}
#define CP_COMMIT()  asm volatile("cp.async.commit_group;" ::: "memory")
#define CP_WAIT(N)   asm volatile("cp.async.wait_group %0;" :: "n"(N) : "memory")

#define ABUF(b)   ((b) * 32768)
#define BBUF(b)   ((b) * 32768 + 16384)
#define SMEM_TOTAL (3 * 32768)
#define STG_LDS   132

__device__ __forceinline__ void split_pack(float a, float b, uint32_t& hi, uint32_t& lo) {
    __nv_bfloat16 ha = __float2bfloat16(a);
    __nv_bfloat16 hb = __float2bfloat16(b);
    __nv_bfloat162 hh; hh.x = ha; hh.y = hb;
    __nv_bfloat162 ll;
    ll.x = __float2bfloat16(a - __bfloat162float(ha));
    ll.y = __float2bfloat16(b - __bfloat162float(hb));
    hi = *reinterpret_cast<uint32_t*>(&hh);
    lo = *reinterpret_cast<uint32_t*>(&ll);
}

// ---------------------------------------------------------------------------
// Symmetric-output batched GEMM on bf16 hi/lo planes, 3-product split.
// bx=0 -> (0,0); 1 -> (0,128) (+ smem-transposed mirror); 2 -> (128,128).
// bx in [3,6): second GEMM of a fused pair (mode forced 0).
// modes: 0 planes; 1 TI planes; 2 fused triu-FC partials; 3 cov (Ahat + ZY)
// b = blockIdx.y + bbase (multi-stream batch slices)
// ---------------------------------------------------------------------------
__global__ __launch_bounds__(256, 2)
void gemm_tc(const __nv_bfloat16* __restrict__ Ahi, const __nv_bfloat16* __restrict__ Alo,
             const __nv_bfloat16* __restrict__ Bhi, const __nv_bfloat16* __restrict__ Blo,
             __nv_bfloat16* __restrict__ Chi, __nv_bfloat16* __restrict__ Clo,
             __nv_bfloat16* __restrict__ C2hi, __nv_bfloat16* __restrict__ C2lo,
             const __nv_bfloat16* A2hi, const __nv_bfloat16* A2lo,
             const __nv_bfloat16* B2hi, const __nv_bfloat16* B2lo,
             __nv_bfloat16* D2hi, __nv_bfloat16* D2lo,
             const float* __restrict__ fcw, float* __restrict__ part,
             int ldk, long strAB, int K, int mode, int bbase,
             const float* __restrict__ norm, const float* __restrict__ sums) {
    extern __shared__ char smem[];
    const uint32_t smb = smem_u32(smem);

    const int tid  = threadIdx.x;
    const int wid  = tid >> 5;
    const int lane = tid & 31;
    const int wm = wid >> 2;
    const int wn = wid & 3;
    const int g  = lane >> 2;
    const int t  = lane & 3;

    int bx = blockIdx.x;
    const int b = blockIdx.y + bbase;

    const __nv_bfloat16 *pAh = Ahi, *pAl = Alo, *pBh = Bhi, *pBl = Blo;
    __nv_bfloat16 *pCh = Chi, *pCl = Clo;
    if (bx >= 3) {
        bx -= 3;
        pAh = A2hi; pAl = A2lo; pBh = B2hi; pBl = B2lo;
        pCh = D2hi; pCl = D2lo;
        mode = 0;
    }
    const int m0 = (bx == 2) ? 128 : 0;
    const int n0 = (bx >= 1) ? 128 : 0;
    const bool offdiag = (m0 != n0);

    const __nv_bfloat16* Abh = pAh + (size_t)b * strAB + (size_t)m0 * ldk;
    const __nv_bfloat16* Abl = pAl + (size_t)b * strAB + (size_t)m0 * ldk;
    const __nv_bfloat16* Bbh = pBh + (size_t)b * strAB + (size_t)n0 * ldk;
    const __nv_bfloat16* Bbl = pBl + (size_t)b * strAB + (size_t)n0 * ldk;

    const int r0c = (tid + 0)   >> 2, c0c = tid & 3;
    const int r1c = (tid + 256) >> 2;
    const int nch = K >> 5;

    float acc[4][4][4];
#pragma unroll
    for (int i = 0; i < 4; ++i)
#pragma unroll
        for (int j = 0; j < 4; ++j)
#pragma unroll
            for (int k = 0; k < 4; ++k) acc[i][j][k] = 0.f;

    auto issue = [&](int ch, int buf) {
        int col = (ch << 5) + c0c * 8;
        uint32_t swh0 = (uint32_t)((c0c       ^ (r0c & 7)) << 4);
        uint32_t swl0 = (uint32_t)(((4 + c0c) ^ (r0c & 7)) << 4);
        uint32_t swh1 = (uint32_t)((c0c       ^ (r1c & 7)) << 4);
        uint32_t swl1 = (uint32_t)(((4 + c0c) ^ (r1c & 7)) << 4);
        uint32_t dA0 = smb + ABUF(buf) + r0c * 128;
        uint32_t dB0 = smb + BBUF(buf) + r0c * 128;
        uint32_t dA1 = smb + ABUF(buf) + r1c * 128;
        uint32_t dB1 = smb + BBUF(buf) + r1c * 128;
        cp16(dA0 + swh0, Abh + (size_t)r0c * ldk + col);
        cp16(dA0 + swl0, Abl + (size_t)r0c * ldk + col);
        cp16(dB0 + swh0, Bbh + (size_t)r0c * ldk + col);
        cp16(dB0 + swl0, Bbl + (size_t)r0c * ldk + col);
        cp16(dA1 + swh1, Abh + (size_t)r1c * ldk + col);
        cp16(dA1 + swl1, Abl + (size_t)r1c * ldk + col);
        cp16(dB1 + swh1, Bbh + (size_t)r1c * ldk + col);
        cp16(dB1 + swl1, Bbl + (size_t)r1c * ldk + col);
    };

    issue(0, 0); CP_COMMIT();
    if (nch > 1) { issue(1, 1); CP_COMMIT(); }

    for (int ch = 0; ch < nch; ++ch) {
        if (ch + 1 < nch) { CP_WAIT(1); } else { CP_WAIT(0); }
        __syncthreads();
        if (ch + 2 < nch) { issue(ch + 2, (ch + 2) % 3); CP_COMMIT(); }

        const int buf = ch % 3;
        const uint32_t smA = smb + ABUF(buf);
        const uint32_t smB = smb + BBUF(buf);

#pragma unroll
        for (int ks = 0; ks < 2; ++ks) {
            uint32_t ah[4][4], al[4][4];
#pragma unroll
            for (int mt = 0; mt < 4; ++mt) {
                int r = wm * 64 + mt * 16 + (lane & 15);
                int cb = ks * 2 + (lane >> 4);
                ldsm4(smA + r * 128 + ((cb       ^ (r & 7)) << 4), ah[mt]);
                ldsm4(smA + r * 128 + (((4 + cb) ^ (r & 7)) << 4), al[mt]);
            }
            uint32_t bh[2][4], bl[2][4];
#pragma unroll
            for (int bt = 0; bt < 2; ++bt) {
                int r = wn * 32 + bt * 16 + ((lane >> 4) << 3) + (lane & 7);
                int cb = ks * 2 + ((lane >> 3) & 1);
                ldsm4(smB + r * 128 + ((cb       ^ (r & 7)) << 4), bh[bt]);
                ldsm4(smB + r * 128 + (((4 + cb) ^ (r & 7)) << 4), bl[bt]);
            }
#pragma unroll
            for (int mt = 0; mt < 4; ++mt)
#pragma unroll
                for (int nt = 0; nt < 4; ++nt) {
                    const uint32_t* bhp = &bh[nt >> 1][(nt & 1) * 2];
                    mma_bf16(acc[mt][nt], ah[mt], bhp[0], bhp[1]);
                }
#pragma unroll
            for (int mt = 0; mt < 4; ++mt)
#pragma unroll
                for (int nt = 0; nt < 4; ++nt) {
                    const uint32_t* blp = &bl[nt >> 1][(nt & 1) * 2];
                    mma_bf16(acc[mt][nt], ah[mt], blp[0], blp[1]);
                }
#pragma unroll
            for (int mt = 0; mt < 4; ++mt)
#pragma unroll
                for (int nt = 0; nt < 4; ++nt) {
                    const uint32_t* bhp = &bh[nt >> 1][(nt & 1) * 2];
                    mma_bf16(acc[mt][nt], al[mt], bhp[0], bhp[1]);
                }
        }
    }

    const size_t cbase = (size_t)b * MAT;

    if (mode == 2) {
        float sc = sqrtf(norm[b]);
        float f0 = 0.f, f1 = 0.f;
#pragma unroll
        for (int mt = 0; mt < 4; ++mt) {
            int r0 = m0 + wm * 64 + mt * 16 + g;
#pragma unroll
            for (int nt = 0; nt < 4; ++nt) {
                int c0 = n0 + wn * 32 + nt * 8 + 2 * t;
                float* d = acc[mt][nt];
#pragma unroll
                for (int half = 0; half < 2; ++half) {
                    int gi = r0 + half * 8;
                    float v0 = d[half * 2 + 0] * sc;
                    float v1 = d[half * 2 + 1] * sc;
                    int tt = gi * CCH - ((gi * (gi + 1)) >> 1) + c0;
                    if (offdiag || c0 >= gi) {
                        f0 += v0 * __ldg(fcw + tt);
                        f1 += v0 * __ldg(fcw + DTRI + tt);
                    }
                    if (offdiag || c0 + 1 >= gi) {
                        f0 += v1 * __ldg(fcw + tt + 1);
                        f1 += v1 * __ldg(fcw + DTRI + tt + 1);
                    }
                }
            }
        }
        __syncthreads();
        float* red = reinterpret_cast<float*>(smem);
        red[tid] = f0; red[256 + tid] = f1;
        __syncthreads();
        for (int off = 128; off > 0; off >>= 1) {
            if (tid < off) { red[tid] += red[tid + off]; red[256 + tid] += red[256 + tid + off]; }
            __syncthreads();
        }
        if (tid == 0) {
            part[(b * 3 + bx) * 2 + 0] = red[0];
            part[(b * 3 + bx) * 2 + 1] = red[256];
        }
        return;
    }

    float invMn = 0.0f;
    const float* sb = 0;
    if (mode == 3) {
        invMn = 1.0f / (196.0f * norm[b]);
        sb = sums + b * CCH;
    }

    __syncthreads();
    float* stg = reinterpret_cast<float*>(smem);

#pragma unroll
    for (int mt = 0; mt < 4; ++mt) {
        int r0 = m0 + wm * 64 + mt * 16 + g;
#pragma unroll
        for (int nt = 0; nt < 4; ++nt) {
            int c0 = n0 + wn * 32 + nt * 8 + 2 * t;
            float* d = acc[mt][nt];
#pragma unroll
            for (int half = 0; half < 2; ++half) {
                int gi = r0 + half * 8;
                float v0 = d[half * 2 + 0];
                float v1 = d[half * 2 + 1];
                size_t off = cbase + (size_t)gi * CCH + c0;
                if (mode == 1) {
                    v0 = (gi == c0     ? 1.5f : 0.0f) - 0.5f * v0;
                    v1 = (gi == c0 + 1 ? 1.5f : 0.0f) - 0.5f * v1;
                } else if (mode == 3) {
                    float si = sb[gi] * (1.0f / 196.0f);
                    v0 = (v0 - si * sb[c0])     * invMn;
                    v1 = (v1 - si * sb[c0 + 1]) * invMn;
                    float w0 = (gi == c0     ? 1.5f : 0.0f) - 0.5f * v0;
                    float w1 = (gi == c0 + 1 ? 1.5f : 0.0f) - 0.5f * v1;
                    uint32_t whi, wlo;
                    split_pack(w0, w1, whi, wlo);
                    *reinterpret_cast<uint32_t*>(C2hi + off) = whi;
                    *reinterpret_cast<uint32_t*>(C2lo + off) = wlo;
                }
                uint32_t hi, lo;
                split_pack(v0, v1, hi, lo);
                *reinterpret_cast<uint32_t*>(pCh + off) = hi;
                *reinterpret_cast<uint32_t*>(pCl + off) = lo;
                if (offdiag) {
                    int lr = gi - m0, lc = c0 - n0;
                    stg[lr * STG_LDS + lc]     = v0;
                    stg[lr * STG_LDS + lc + 1] = v1;
                }
            }
        }
    }

    if (offdiag) {
        __syncthreads();
        const int j  = tid & 127;
        const int ib = tid >> 7;
#pragma unroll
        for (int s = 0; s < 8; ++s) {
            int i0 = ib * 64 + s * 8;
            uint32_t hp[4], lp[4], wh[4], wl[4];
#pragma unroll
            for (int k = 0; k < 4; ++k) {
                float a = stg[(i0 + 2 * k)     * STG_LDS + j];
                float c = stg[(i0 + 2 * k + 1) * STG_LDS + j];
                split_pack(a, c, hp[k], lp[k]);
                if (mode == 3) split_pack(-0.5f * a, -0.5f * c, wh[k], wl[k]);
            }
            size_t moff = cbase + (size_t)(n0 + j) * CCH + (m0 + i0);
            *reinterpret_cast<uint4*>(pCh + moff) = make_uint4(hp[0], hp[1], hp[2], hp[3]);
            *reinterpret_cast<uint4*>(pCl + moff) = make_uint4(lp[0], lp[1], lp[2], lp[3]);
            if (mode == 3) {
                *reinterpret_cast<uint4*>(C2hi + moff) = make_uint4(wh[0], wh[1], wh[2], wh[3]);
                *reinterpret_cast<uint4*>(C2lo + moff) = make_uint4(wl[0], wl[1], wl[2], wl[3]);
            }
        }
    }
}

// ---------------------------------------------------------------------------
// Per-quarter prep: 8 rows per block, offset by bbase batches.
__global__ __launch_bounds__(256)
void split_x_kernel(const float* __restrict__ x,
                    __nv_bfloat16* __restrict__ xhi, __nv_bfloat16* __restrict__ xlo,
                    int rowbase) {
    int row = rowbase + blockIdx.x * 8 + (threadIdx.x >> 5);
    int lane = threadIdx.x & 31;
    const float* src = x + (size_t)row * MMSP;
    __nv_bfloat16* dh = xhi + (size_t)row * KPAD;
    __nv_bfloat16* dl = xlo + (size_t)row * KPAD;
#pragma unroll
    for (int m = lane; m < KPAD; m += 32) {
        float v = (m < MMSP) ? src[m] : 0.f;
        __nv_bfloat16 h = __float2bfloat16(v);
        dh[m] = h;
        dl[m] = __float2bfloat16(v - __bfloat162float(h));
    }
}

__global__ void rowsum_norm_kernel(const float* __restrict__ x,
                                   float* __restrict__ s, float* __restrict__ nrm,
                                   int bbase) {
    int b = blockIdx.x + bbase, c = threadIdx.x;
    const float* p = x + ((size_t)b * CCH + c) * MMSP;
    float sum = 0.f, q = 0.f;
#pragma unroll 4
    for (int m = 0; m < MMSP; ++m) { float v = p[m]; sum += v; q += v * v; }
    s[b * CCH + c] = sum;
    float part = q - sum * sum * (1.0f / 196.0f);
    __shared__ float sh[8];
#pragma unroll
    for (int o = 16; o > 0; o >>= 1) part += __shfl_down_sync(0xffffffffu, part, o);
    if ((c & 31) == 0) sh[c >> 5] = part;
    __syncthreads();
    if (c < 8) {
        float w = sh[c];
#pragma unroll
        for (int o = 4; o > 0; o >>= 1) w += __shfl_down_sync(0xffu, w, o);
        if (c == 0) nrm[b] = w * (1.0f / 196.0f);
    }
}

__global__ void finish_kernel(const float* __restrict__ part,
                              const float* __restrict__ bias, float* __restrict__ out) {
    int i = blockIdx.x * blockDim.x + threadIdx.x;
    int b = i >> 1, k = i & 1;
    out[i] = bias[k] + part[(b * 3 + 0) * 2 + k]
                     + part[(b * 3 + 1) * 2 + k]
                     + part[(b * 3 + 2) * 2 + k];
}

// ---------------------------------------------------------------------------
struct Planes {
    __nv_bfloat16 *Xh, *Xl, *Ph, *Pl, *Qh, *Ql, *Rh, *Rl, *Sh, *Sl, *Th, *Tl;
    float *part, *sums, *nrm;
};

static void run_chain(cudaStream_t st, int bbase, const Planes& p,
                      const float* x, const float* fc_w) {
    dim3 g1(3, QTR);
    dim3 g2(6, QTR);
    const long strX = (long)CCH * KPAD;
    const long strM = (long)MAT;
    const __nv_bfloat16* nbp = 0;
    __nv_bfloat16* nbo = 0;

    // per-quarter prep (overlaps other streams' prep/cov)
    rowsum_norm_kernel<<<QTR, CCH, 0, st>>>(x, p.sums, p.nrm, bbase);
    split_x_kernel<<<QTR * CCH / 8, 256, 0, st>>>(x, p.Xh, p.Xl, bbase * CCH);

    gemm_tc<<<g1, 256, SMEM_TOTAL, st>>>(p.Xh, p.Xl, p.Xh, p.Xl, p.Ph, p.Pl, p.Qh, p.Ql,
                                         nbp, nbp, nbp, nbp, nbo, nbo, (const float*)0, (float*)0,
                                         KPAD, strX, KPAD, 3, bbase, p.nrm, p.sums);
    gemm_tc<<<g1, 256, SMEM_TOTAL, st>>>(p.Ph, p.Pl, p.Qh, p.Ql, p.Rh, p.Rl, nbo, nbo,
                                         nbp, nbp, nbp, nbp, nbo, nbo, (const float*)0, (float*)0,
                                         CCH, strM, CCH, 0, bbase, p.nrm, 0);
    gemm_tc<<<g1, 256, SMEM_TOTAL, st>>>(p.Qh, p.Ql, p.Rh, p.Rl, p.Sh, p.Sl, nbo, nbo,
                                         nbp, nbp, nbp, nbp, nbo, nbo, (const float*)0, (float*)0,
                                         CCH, strM, CCH, 1, bbase, p.nrm, 0);
    gemm_tc<<<g2, 256, SMEM_TOTAL, st>>>(p.Rh, p.Rl, p.Sh, p.Sl, p.Th, p.Tl, nbo, nbo,
                                         p.Sh, p.Sl, p.Qh, p.Ql, p.Ph, p.Pl, (const float*)0, (float*)0,
                                         CCH, strM, CCH, 0, bbase, p.nrm, 0);
    gemm_tc<<<g1, 256, SMEM_TOTAL, st>>>(p.Ph, p.Pl, p.Th, p.Tl, p.Sh, p.Sl, nbo, nbo,
                                         nbp, nbp, nbp, nbp, nbo, nbo, (const float*)0, (float*)0,
                                         CCH, strM, CCH, 1, bbase, p.nrm, 0);
    gemm_tc<<<g2, 256, SMEM_TOTAL, st>>>(p.Th, p.Tl, p.Sh, p.Sl, p.Qh, p.Ql, nbo, nbo,
                                         p.Sh, p.Sl, p.Ph, p.Pl, p.Rh, p.Rl, (const float*)0, (float*)0,
                                         CCH, strM, CCH, 0, bbase, p.nrm, 0);
    gemm_tc<<<g1, 256, SMEM_TOTAL, st>>>(p.Rh, p.Rl, p.Qh, p.Ql, p.Sh, p.Sl, nbo, nbo,
                                         nbp, nbp, nbp, nbp, nbo, nbo, (const float*)0, (float*)0,
                                         CCH, strM, CCH, 1, bbase, p.nrm, 0);
    gemm_tc<<<g2, 256, SMEM_TOTAL, st>>>(p.Qh, p.Ql, p.Sh, p.Sl, p.Th, p.Tl, nbo, nbo,
                                         p.Sh, p.Sl, p.Rh, p.Rl, p.Ph, p.Pl, (const float*)0, (float*)0,
                                         CCH, strM, CCH, 0, bbase, p.nrm, 0);
    gemm_tc<<<g1, 256, SMEM_TOTAL, st>>>(p.Ph, p.Pl, p.Th, p.Tl, p.Sh, p.Sl, nbo, nbo,
                                         nbp, nbp, nbp, nbp, nbo, nbo, (const float*)0, (float*)0,
                                         CCH, strM, CCH, 1, bbase, p.nrm, 0);
    gemm_tc<<<g1, 256, SMEM_TOTAL, st>>>(p.Th, p.Tl, p.Sh, p.Sl, nbo, nbo, nbo, nbo,
                                         nbp, nbp, nbp, nbp, nbo, nbo, fc_w, p.part,
                                         CCH, strM, CCH, 2, bbase, p.nrm, 0);
}

extern "C" void kernel_launch(void* const* d_in, const int* in_sizes, int n_in,
                              void* d_out, int out_size) {
    const float* x    = (const float*)d_in[0];
    const float* fc_w = (const float*)d_in[1];
    const float* fc_b = (const float*)d_in[2];
    float* out        = (float*)d_out;

    Planes p;
    cudaGetSymbolAddress((void**)&p.Xh, g_Xhi); cudaGetSymbolAddress((void**)&p.Xl, g_Xlo);
    cudaGetSymbolAddress((void**)&p.Ph, g_Phi); cudaGetSymbolAddress((void**)&p.Pl, g_Plo);
    cudaGetSymbolAddress((void**)&p.Qh, g_Qhi); cudaGetSymbolAddress((void**)&p.Ql, g_Qlo);
    cudaGetSymbolAddress((void**)&p.Rh, g_Rhi); cudaGetSymbolAddress((void**)&p.Rl, g_Rlo);
    cudaGetSymbolAddress((void**)&p.Sh, g_Shi); cudaGetSymbolAddress((void**)&p.Sl, g_Slo);
    cudaGetSymbolAddress((void**)&p.Th, g_Thi); cudaGetSymbolAddress((void**)&p.Tl, g_Tlo);
    cudaGetSymbolAddress((void**)&p.part, g_part);
    cudaGetSymbolAddress((void**)&p.sums, g_sums);
    cudaGetSymbolAddress((void**)&p.nrm, g_norm);

    cudaFuncSetAttribute(gemm_tc, cudaFuncAttributeMaxDynamicSharedMemorySize, SMEM_TOTAL);

    // Fork at the very top: each stream preps + runs its own batch quarter.
    cudaStream_t s[NSTREAMS - 1];
    cudaEvent_t evFork, evJoin[NSTREAMS - 1];
    for (int i = 0; i < NSTREAMS - 1; ++i)
        cudaStreamCreateWithFlags(&s[i], cudaStreamNonBlocking);
    cudaEventCreateWithFlags(&evFork, cudaEventDisableTiming);
    for (int i = 0; i < NSTREAMS - 1; ++i)
        cudaEventCreateWithFlags(&evJoin[i], cudaEventDisableTiming);

    cudaEventRecord(evFork, 0);
    for (int i = 0; i < NSTREAMS - 1; ++i)
        cudaStreamWaitEvent(s[i], evFork, 0);

    run_chain((cudaStream_t)0, 0 * QTR, p, x, fc_w);
    for (int i = 0; i < NSTREAMS - 1; ++i)
        run_chain(s[i], (i + 1) * QTR, p, x, fc_w);

    for (int i = 0; i < NSTREAMS - 1; ++i) {
        cudaEventRecord(evJoin[i], s[i]);
        cudaStreamWaitEvent((cudaStream_t)0, evJoin[i], 0);
    }

    finish_kernel<<<2, 256>>>(p.part, fc_b, out);

    for (int i = 0; i < NSTREAMS - 1; ++i) {
        cudaStreamDestroy(s[i]);
        cudaEventDestroy(evJoin[i]);
    }
    cudaEventDestroy(evFork);
}